// round 10
// baseline (speedup 1.0000x reference)
#include <cuda_runtime.h>
#include <cuda_bf16.h>
#include <stdint.h>

typedef unsigned long long u64;
typedef unsigned int u32;

#define BB 2
#define TT 2048
#define CC 1024
#define HQ 16
#define HKV 2
#define HD 64
#define MROWS (BB*TT)   // 4096

// ---------------------------------------------------------------------------
// Scratch (device globals; allocation APIs are forbidden)
// ---------------------------------------------------------------------------
__device__ __nv_bfloat16 g_xh[MROWS*CC], g_xl[MROWS*CC];
__device__ __nv_bfloat16 g_yh[MROWS*CC], g_yl[MROWS*CC];
__device__ __nv_bfloat16 g_wqh[CC*CC],  g_wql[CC*CC];
__device__ __nv_bfloat16 g_wkh[HKV*HD*CC], g_wkl[HKV*HD*CC];
__device__ __nv_bfloat16 g_wvh[HKV*HD*CC], g_wvl[HKV*HD*CC];
__device__ __nv_bfloat16 g_woh[CC*CC],  g_wol[CC*CC];

// split-bf16 Q/K (row-major) and V (transposed [b][hk][d][t])
__device__ __nv_bfloat16 g_qbh[MROWS*HQ*HD],  g_qbl[MROWS*HQ*HD];
__device__ __nv_bfloat16 g_kbh[MROWS*HKV*HD], g_kbl[MROWS*HKV*HD];
__device__ __nv_bfloat16 g_vth[BB*HKV*HD*TT], g_vtl[BB*HKV*HD*TT];

// ---------------------------------------------------------------------------
__device__ __forceinline__ u32 smem_to_u32(const void* p) {
    u32 a;
    asm("{ .reg .u64 tmp; cvta.to.shared.u64 tmp, %1; cvt.u32.u64 %0, tmp; }"
        : "=r"(a) : "l"(p));
    return a;
}
__device__ __forceinline__ void ldm_x4(u32* r, u32 addr) {
    asm volatile("ldmatrix.sync.aligned.m8n8.x4.shared.b16 {%0,%1,%2,%3}, [%4];"
        : "=r"(r[0]), "=r"(r[1]), "=r"(r[2]), "=r"(r[3]) : "r"(addr));
}
__device__ __forceinline__ void hmma(float* d, const u32* a, const u32* b) {
    asm volatile("mma.sync.aligned.m16n8k16.row.col.f32.bf16.bf16.f32 "
        "{%0,%1,%2,%3}, {%4,%5,%6,%7}, {%8,%9}, {%0,%1,%2,%3};"
        : "+f"(d[0]), "+f"(d[1]), "+f"(d[2]), "+f"(d[3])
        : "r"(a[0]), "r"(a[1]), "r"(a[2]), "r"(a[3]), "r"(b[0]), "r"(b[1]));
}
__device__ __forceinline__ u32 cvt2(float hi, float lo) {
    u32 r; asm("cvt.rn.bf16x2.f32 %0, %1, %2;" : "=r"(r) : "f"(hi), "f"(lo));
    return r;
}

// ---------------------------------------------------------------------------
// Split fp32 -> (hi, lo) bf16
// ---------------------------------------------------------------------------
__device__ __forceinline__ void split_body(
    const float* __restrict__ src, __nv_bfloat16* __restrict__ h,
    __nv_bfloat16* __restrict__ l, int i)
{
    float4 v = ((const float4*)src)[i];
    float vv[4] = { v.x, v.y, v.z, v.w };
    __nv_bfloat162 hh[2], ll[2];
    #pragma unroll
    for (int j = 0; j < 2; ++j) {
        __nv_bfloat16 h0 = __float2bfloat16(vv[2*j]);
        __nv_bfloat16 h1 = __float2bfloat16(vv[2*j+1]);
        hh[j].x = h0; hh[j].y = h1;
        ll[j].x = __float2bfloat16(vv[2*j]   - __bfloat162float(h0));
        ll[j].y = __float2bfloat16(vv[2*j+1] - __bfloat162float(h1));
    }
    ((__nv_bfloat162*)h)[2*i]   = hh[0];
    ((__nv_bfloat162*)h)[2*i+1] = hh[1];
    ((__nv_bfloat162*)l)[2*i]   = ll[0];
    ((__nv_bfloat162*)l)[2*i+1] = ll[1];
}

__global__ void split_kernel(const float* __restrict__ src,
                             __nv_bfloat16* __restrict__ h,
                             __nv_bfloat16* __restrict__ l, int n4)
{
    int i = blockIdx.x * blockDim.x + threadIdx.x;
    if (i >= n4) return;
    split_body(src, h, l, i);
}

// All four weights in one launch (sizes in float4 units)
#define WQ4 (CC*CC/4)          // 262144
#define WK4 (HKV*HD*CC/4)      // 32768
__global__ void split_w_kernel(const float* __restrict__ Wq,
                               const float* __restrict__ Wk,
                               const float* __restrict__ Wv,
                               const float* __restrict__ Wo)
{
    int i = blockIdx.x * blockDim.x + threadIdx.x;
    if (i < WQ4) { split_body(Wq, g_wqh, g_wql, i); return; }
    i -= WQ4;
    if (i < WK4) { split_body(Wk, g_wkh, g_wkl, i); return; }
    i -= WK4;
    if (i < WK4) { split_body(Wv, g_wvh, g_wvl, i); return; }
    i -= WK4;
    if (i < WQ4) { split_body(Wo, g_woh, g_wol, i); return; }
}

// ---------------------------------------------------------------------------
// HMMA bf16 split-GEMM tile: acc[128,128] = A[128,K].B[128,K]^T (+bias)
// mode 0: fp32 out (no rope)
// mode 1: rope + split-bf16 row-major out (Q, K)
// mode 2: split-bf16 transposed out for V ([b][hk][d][t])
// Single-stage smem (73.7KB -> 2 CTAs/SM); register prefetch bridges syncs.
// ---------------------------------------------------------------------------
#define SPB 144
#define MAT_BYTES (128*SPB)
#define HMMA_SMEM (4*MAT_BYTES)         // 73728

__device__ __forceinline__ void hmma_tile_128(
    const __nv_bfloat16* __restrict__ Ah, const __nv_bfloat16* __restrict__ Al,
    const __nv_bfloat16* __restrict__ Bh, const __nv_bfloat16* __restrict__ Bl,
    const float* __restrict__ bias, const float* __restrict__ rc,
    int m0, int n0, int ldo, int mode, float postscale,
    float* __restrict__ outf,
    __nv_bfloat16* __restrict__ outh, __nv_bfloat16* __restrict__ outl)
{
    extern __shared__ char smem[];
    const u32 sbase = smem_to_u32(smem);
    const int tid = threadIdx.x;
    const int wid = tid >> 5, L = tid & 31;
    const int wm = (wid >> 2) * 64;
    const int wn = (wid & 3) * 32;

    const u32 aRow = (u32)(wm + (L & 15)) * SPB + ((L >> 4) & 1) * 16;
    const u32 bRow = (u32)(wn + (((L >> 4) & 1) << 3) + (L & 7)) * SPB
                   + ((L >> 3) & 1) * 16;

    float acc[4][4][4];
    #pragma unroll
    for (int i = 0; i < 4; ++i)
        #pragma unroll
        for (int j = 0; j < 4; ++j)
            #pragma unroll
            for (int c = 0; c < 4; ++c) acc[i][j][c] = 0.f;

    float4 pA[4], pAl[4], pB[4], pBl[4];

    // prologue: stage slab 0
    #pragma unroll
    for (int i = 0; i < 4; ++i) {
        const int it = tid + 256*i;
        const int row = it >> 3, ch = it & 7;
        const size_t ga = (size_t)(m0 + row) * CC + ch*8;
        const size_t gb = (size_t)(n0 + row) * CC + ch*8;
        const u32 so = (u32)row * SPB + ch*16;
        *(float4*)(smem + so)               = *(const float4*)(Ah + ga);
        *(float4*)(smem + MAT_BYTES + so)   = *(const float4*)(Al + ga);
        *(float4*)(smem + 2*MAT_BYTES + so) = *(const float4*)(Bh + gb);
        *(float4*)(smem + 3*MAT_BYTES + so) = *(const float4*)(Bl + gb);
    }
    __syncthreads();

    const int nslab = CC / 64;
    for (int s = 0; s < nslab; ++s) {
        const bool more = (s + 1 < nslab);
        if (more) {
            const int k0 = (s + 1) * 64;
            #pragma unroll
            for (int i = 0; i < 4; ++i) {
                const int it = tid + 256*i;
                const int row = it >> 3, ch = it & 7;
                const size_t ga = (size_t)(m0 + row) * CC + k0 + ch*8;
                const size_t gb = (size_t)(n0 + row) * CC + k0 + ch*8;
                pA[i]  = *(const float4*)(Ah + ga);
                pAl[i] = *(const float4*)(Al + ga);
                pB[i]  = *(const float4*)(Bh + gb);
                pBl[i] = *(const float4*)(Bl + gb);
            }
        }

        const u32 aAh = sbase + aRow;
        const u32 aAl = sbase + MAT_BYTES + aRow;
        const u32 aBh = sbase + 2*MAT_BYTES + bRow;
        const u32 aBl = sbase + 3*MAT_BYTES + bRow;

        #pragma unroll
        for (int ks = 0; ks < 4; ++ks) {
            u32 ah[4][4], al[4][4], bh[4][2], bl[4][2];
            #pragma unroll
            for (int mt = 0; mt < 4; ++mt) {
                ldm_x4(ah[mt], aAh + mt*(16*SPB) + ks*32);
                ldm_x4(al[mt], aAl + mt*(16*SPB) + ks*32);
            }
            #pragma unroll
            for (int np = 0; np < 2; ++np) {
                u32 r[4];
                ldm_x4(r, aBh + np*(16*SPB) + ks*32);
                bh[2*np][0] = r[0]; bh[2*np][1] = r[1];
                bh[2*np+1][0] = r[2]; bh[2*np+1][1] = r[3];
                ldm_x4(r, aBl + np*(16*SPB) + ks*32);
                bl[2*np][0] = r[0]; bl[2*np][1] = r[1];
                bl[2*np+1][0] = r[2]; bl[2*np+1][1] = r[3];
            }
            #pragma unroll
            for (int mt = 0; mt < 4; ++mt)
                #pragma unroll
                for (int nt = 0; nt < 4; ++nt) {
                    hmma(acc[mt][nt], ah[mt], bh[nt]);
                    hmma(acc[mt][nt], ah[mt], bl[nt]);
                    hmma(acc[mt][nt], al[mt], bh[nt]);
                }
        }

        if (more) {
            __syncthreads();   // all warps done reading current slab
            #pragma unroll
            for (int i = 0; i < 4; ++i) {
                const int it = tid + 256*i;
                const int row = it >> 3, ch = it & 7;
                const u32 so = (u32)row * SPB + ch*16;
                *(float4*)(smem + so)               = pA[i];
                *(float4*)(smem + MAT_BYTES + so)   = pAl[i];
                *(float4*)(smem + 2*MAT_BYTES + so) = pB[i];
                *(float4*)(smem + 3*MAT_BYTES + so) = pBl[i];
            }
            __syncthreads();
        }
    }

    // Epilogue
    #pragma unroll
    for (int mt = 0; mt < 4; ++mt) {
        #pragma unroll
        for (int nt = 0; nt < 4; ++nt) {
            const int n = n0 + wn + nt*8 + (L & 3) * 2;
            const float2 bv = *(const float2*)(bias + n);
            #pragma unroll
            for (int half = 0; half < 2; ++half) {
                const int r = m0 + wm + mt*16 + (L >> 2) + half*8;
                float v0 = acc[mt][nt][2*half]   + bv.x;
                float v1 = acc[mt][nt][2*half+1] + bv.y;
                if (mode == 1) {
                    const int t = r & (TT - 1);
                    const int d = n & (HD - 1);
                    const float2 rcv = *(const float2*)(rc + t*HD + d);
                    const float o0 = (v0 * rcv.y - v1 * rcv.x) * postscale;
                    const float o1 = (v1 * rcv.y + v0 * rcv.x) * postscale;
                    v0 = o0; v1 = o1;
                }
                if (mode == 0) {
                    float2 sv; sv.x = v0; sv.y = v1;
                    *(float2*)(outf + (size_t)r * ldo + n) = sv;
                } else {
                    const __nv_bfloat16 h0 = __float2bfloat16(v0);
                    const __nv_bfloat16 h1 = __float2bfloat16(v1);
                    const __nv_bfloat16 l0 = __float2bfloat16(v0 - __bfloat162float(h0));
                    const __nv_bfloat16 l1 = __float2bfloat16(v1 - __bfloat162float(h1));
                    if (mode == 1) {
                        __nv_bfloat162 hh; hh.x = h0; hh.y = h1;
                        __nv_bfloat162 ll; ll.x = l0; ll.y = l1;
                        *(__nv_bfloat162*)(outh + (size_t)r * ldo + n) = hh;
                        *(__nv_bfloat162*)(outl + (size_t)r * ldo + n) = ll;
                    } else {  // mode 2: V transposed [b][hk][d][t]
                        const int bb = r >> 11, t = r & (TT - 1);
                        const int hkv = n >> 6, d = n & (HD - 1);
                        const size_t base = (((size_t)bb*HKV + hkv)*HD + d)*TT + t;
                        outh[base] = h0; outh[base + TT] = h1;
                        outl[base] = l0; outl[base + TT] = l1;
                    }
                }
            }
        }
    }
}

// grid (10, 32): x 0..7 -> Q col tiles, 8 -> K, 9 -> V
__global__ __launch_bounds__(256, 2) void qkv_hmma_kernel(
    const float* __restrict__ rc,
    const float* __restrict__ bq, const float* __restrict__ bk,
    const float* __restrict__ bv)
{
    const int nb = blockIdx.x, m0 = blockIdx.y * 128;
    if (nb < 8)
        hmma_tile_128(g_xh, g_xl, g_wqh, g_wql, bq, rc, m0, nb*128, HQ*HD,
                      1, 1.0f/(float)HD, nullptr, g_qbh, g_qbl);
    else if (nb == 8)
        hmma_tile_128(g_xh, g_xl, g_wkh, g_wkl, bk, rc, m0, 0, HKV*HD,
                      1, 1.0f, nullptr, g_kbh, g_kbl);
    else
        hmma_tile_128(g_xh, g_xl, g_wvh, g_wvl, bv, nullptr, m0, 0, HKV*HD,
                      2, 1.0f, nullptr, g_vth, g_vtl);
}

__global__ __launch_bounds__(256, 2) void oproj_hmma_kernel(
    const float* __restrict__ bo, float* __restrict__ out)
{
    hmma_tile_128(g_yh, g_yl, g_woh, g_wol, bo, nullptr,
                  blockIdx.y*128, blockIdx.x*128, CC, 0, 1.0f,
                  out, nullptr, nullptr);
}

// ---------------------------------------------------------------------------
// Flash attention on HMMA. grid (T/64, HQ, B), 128 threads (4 warps).
// Warp w owns q-rows 16w..16w+15. BK=64. 3-term split-bf16 for S and PV.
// O accumulated transposed (O^T = V^T P^T); P stays in registers.
// Writes O as split-bf16 directly into g_yh/g_yl.
// ---------------------------------------------------------------------------
#define FP 72                       // smem pitch in bf16 (144 B)
#define MATB (64*FP*2)              // 9216 B per matrix
#define FLASH_SMEM (6*MATB)         // 55296 B

__global__ __launch_bounds__(128) void flash_hmma_kernel()
{
    extern __shared__ __nv_bfloat16 fsm[];
    const u32 sb = smem_to_u32(fsm);
    // matrices: Qh@0, Ql@MATB, Kh@2*MATB, Kl@3*MATB, Vth@4*MATB, Vtl@5*MATB

    const int qb = blockIdx.x, hq = blockIdx.y, b = blockIdx.z;
    const int qs = qb * 64;
    const int hk = hq / (HQ / HKV);
    const int tid = threadIdx.x, wid = tid >> 5, L = tid & 31;

    // stage Q (64 rows x 64 bf16, hi+lo)
    for (int it = tid; it < 512; it += 128) {
        const int row = it >> 3, ch = it & 7;
        const size_t src = (((size_t)b*TT + qs + row)*HQ + hq)*HD + ch*8;
        *(float4*)&fsm[row*FP + ch*8]            = *(const float4*)(g_qbh + src);
        *(float4*)&fsm[64*FP + row*FP + ch*8]    = *(const float4*)(g_qbl + src);
    }

    // fragment address offsets (bytes)
    const u32 aQoff = (u32)((wid*16 + (L & 15)) * SPB) + ((L >> 4) & 1) * 16;
    const u32 aVrow = (u32)((L & 15) * SPB) + ((L >> 4) & 1) * 16;
    const u32 bKoff = (u32)((((L >> 4) & 1) * 8 + (L & 7)) * SPB) + ((L >> 3) & 1) * 16;

    float m0 = -1e30f, m1 = -1e30f, ls0 = 0.f, ls1 = 0.f;
    float oacc[4][2][4];
    #pragma unroll
    for (int i = 0; i < 4; ++i)
        #pragma unroll
        for (int j = 0; j < 2; ++j)
            #pragma unroll
            for (int c = 0; c < 4; ++c) oacc[i][j][c] = 0.f;

    for (int kt = 0; kt <= qb; ++kt) {
        __syncthreads();
        // stage K (rows t), V^T (rows d)
        for (int it = tid; it < 512; it += 128) {
            const int row = it >> 3, ch = it & 7;
            const size_t ks = (((size_t)b*TT + kt*64 + row)*HKV + hk)*HD + ch*8;
            const size_t vs = (((size_t)b*HKV + hk)*HD + row)*TT + kt*64 + ch*8;
            *(float4*)&fsm[2*64*FP + row*FP + ch*8] = *(const float4*)(g_kbh + ks);
            *(float4*)&fsm[3*64*FP + row*FP + ch*8] = *(const float4*)(g_kbl + ks);
            *(float4*)&fsm[4*64*FP + row*FP + ch*8] = *(const float4*)(g_vth + vs);
            *(float4*)&fsm[5*64*FP + row*FP + ch*8] = *(const float4*)(g_vtl + vs);
        }
        __syncthreads();

        // ---- S = Q.K^T (3-term) ----
        float sacc[8][4];
        #pragma unroll
        for (int nt = 0; nt < 8; ++nt)
            #pragma unroll
            for (int c = 0; c < 4; ++c) sacc[nt][c] = 0.f;

        #pragma unroll
        for (int ks = 0; ks < 4; ++ks) {
            u32 qh_[4], ql_[4];
            ldm_x4(qh_, sb + aQoff + ks*32);
            ldm_x4(ql_, sb + MATB + aQoff + ks*32);
            #pragma unroll
            for (int np = 0; np < 4; ++np) {
                u32 rh[4], rl[4];
                const u32 bo = (u32)(np*16*SPB) + bKoff + ks*32;
                ldm_x4(rh, sb + 2*MATB + bo);
                ldm_x4(rl, sb + 3*MATB + bo);
                u32 bh0[2] = { rh[0], rh[1] }, bh1[2] = { rh[2], rh[3] };
                u32 bl0[2] = { rl[0], rl[1] }, bl1[2] = { rl[2], rl[3] };
                hmma(sacc[2*np],   qh_, bh0);
                hmma(sacc[2*np],   qh_, bl0);
                hmma(sacc[2*np],   ql_, bh0);
                hmma(sacc[2*np+1], qh_, bh1);
                hmma(sacc[2*np+1], qh_, bl1);
                hmma(sacc[2*np+1], ql_, bh1);
            }
        }

        // ---- causal mask (diagonal tile only) ----
        if (kt == qb) {
            #pragma unroll
            for (int nt = 0; nt < 8; ++nt)
                #pragma unroll
                for (int c = 0; c < 4; ++c) {
                    const int col = nt*8 + (L & 3)*2 + (c & 1);
                    const int row = wid*16 + (L >> 2) + ((c >> 1) & 1)*8;
                    if (col > row) sacc[nt][c] = -1e30f;
                }
        }

        // ---- online softmax ----
        float mx0 = -1e30f, mx1 = -1e30f;
        #pragma unroll
        for (int nt = 0; nt < 8; ++nt) {
            mx0 = fmaxf(mx0, fmaxf(sacc[nt][0], sacc[nt][1]));
            mx1 = fmaxf(mx1, fmaxf(sacc[nt][2], sacc[nt][3]));
        }
        mx0 = fmaxf(mx0, __shfl_xor_sync(0xffffffffu, mx0, 1));
        mx0 = fmaxf(mx0, __shfl_xor_sync(0xffffffffu, mx0, 2));
        mx1 = fmaxf(mx1, __shfl_xor_sync(0xffffffffu, mx1, 1));
        mx1 = fmaxf(mx1, __shfl_xor_sync(0xffffffffu, mx1, 2));
        const float nm0 = fmaxf(m0, mx0);
        const float nm1 = fmaxf(m1, mx1);
        const float corr0 = __expf(m0 - nm0);
        const float corr1 = __expf(m1 - nm1);
        m0 = nm0; m1 = nm1;

        u32 ph0[8], ph1[8], pl0[8], pl1[8];
        float rs0 = 0.f, rs1 = 0.f;
        #pragma unroll
        for (int nt = 0; nt < 8; ++nt) {
            const float p00 = __expf(sacc[nt][0] - nm0);
            const float p01 = __expf(sacc[nt][1] - nm0);
            const float p10 = __expf(sacc[nt][2] - nm1);
            const float p11 = __expf(sacc[nt][3] - nm1);
            rs0 += p00 + p01;
            rs1 += p10 + p11;
            ph0[nt] = cvt2(p01, p00);
            ph1[nt] = cvt2(p11, p10);
            pl0[nt] = cvt2(p01 - __bfloat162float(__float2bfloat16(p01)),
                           p00 - __bfloat162float(__float2bfloat16(p00)));
            pl1[nt] = cvt2(p11 - __bfloat162float(__float2bfloat16(p11)),
                           p10 - __bfloat162float(__float2bfloat16(p10)));
        }
        rs0 += __shfl_xor_sync(0xffffffffu, rs0, 1);
        rs0 += __shfl_xor_sync(0xffffffffu, rs0, 2);
        rs1 += __shfl_xor_sync(0xffffffffu, rs1, 1);
        rs1 += __shfl_xor_sync(0xffffffffu, rs1, 2);
        ls0 = ls0 * corr0 + rs0;
        ls1 = ls1 * corr1 + rs1;

        // rescale O^T accumulators
        float cr[2][2];
        cr[0][0] = __shfl_sync(0xffffffffu, corr0, ((L & 3)*2)     << 2);
        cr[0][1] = __shfl_sync(0xffffffffu, corr0, ((L & 3)*2 + 1) << 2);
        cr[1][0] = __shfl_sync(0xffffffffu, corr1, ((L & 3)*2)     << 2);
        cr[1][1] = __shfl_sync(0xffffffffu, corr1, ((L & 3)*2 + 1) << 2);
        #pragma unroll
        for (int mt = 0; mt < 4; ++mt)
            #pragma unroll
            for (int nu = 0; nu < 2; ++nu)
                #pragma unroll
                for (int c = 0; c < 4; ++c)
                    oacc[mt][nu][c] *= cr[nu][c & 1];

        // ---- O^T += V^T.P^T (3-term) ----
        #pragma unroll
        for (int k2 = 0; k2 < 4; ++k2) {
            u32 bH0[2] = { ph0[2*k2], ph0[2*k2+1] };
            u32 bH1[2] = { ph1[2*k2], ph1[2*k2+1] };
            u32 bL0[2] = { pl0[2*k2], pl0[2*k2+1] };
            u32 bL1[2] = { pl1[2*k2], pl1[2*k2+1] };
            #pragma unroll
            for (int mt = 0; mt < 4; ++mt) {
                u32 vh_[4], vl_[4];
                const u32 vo = aVrow + (u32)(mt*16*SPB) + k2*32;
                ldm_x4(vh_, sb + 4*MATB + vo);
                ldm_x4(vl_, sb + 5*MATB + vo);
                hmma(oacc[mt][0], vh_, bH0);
                hmma(oacc[mt][0], vl_, bH0);
                hmma(oacc[mt][0], vh_, bL0);
                hmma(oacc[mt][1], vh_, bH1);
                hmma(oacc[mt][1], vl_, bH1);
                hmma(oacc[mt][1], vh_, bL1);
            }
        }
    }

    // ---- normalize + write split-bf16 O into g_yh/g_yl ([b][t][h][d]) ----
    const float rl0 = 1.f / ls0, rl1 = 1.f / ls1;
    float iv[2][2];
    iv[0][0] = __shfl_sync(0xffffffffu, rl0, ((L & 3)*2)     << 2);
    iv[0][1] = __shfl_sync(0xffffffffu, rl0, ((L & 3)*2 + 1) << 2);
    iv[1][0] = __shfl_sync(0xffffffffu, rl1, ((L & 3)*2)     << 2);
    iv[1][1] = __shfl_sync(0xffffffffu, rl1, ((L & 3)*2 + 1) << 2);
    #pragma unroll
    for (int mt = 0; mt < 4; ++mt)
        #pragma unroll
        for (int nu = 0; nu < 2; ++nu)
            #pragma unroll
            for (int c = 0; c < 4; ++c) {
                const int d = mt*16 + (L >> 2) + ((c >> 1) & 1)*8;
                const int i = nu*8 + (L & 3)*2 + (c & 1);
                const float o = oacc[mt][nu][c] * iv[nu][c & 1];
                const __nv_bfloat16 oh = __float2bfloat16(o);
                const __nv_bfloat16 ol = __float2bfloat16(o - __bfloat162float(oh));
                const size_t idx =
                    (((size_t)b*TT + qs + wid*16 + i)*HQ + hq)*HD + d;
                g_yh[idx] = oh;
                g_yl[idx] = ol;
            }
}

// ---------------------------------------------------------------------------
extern "C" void kernel_launch(void* const* d_in, const int* in_sizes, int n_in,
                              void* d_out, int out_size)
{
    const float* x  = (const float*)d_in[0];
    const float* rc = (const float*)d_in[1];
    const float* Wq = (const float*)d_in[2];
    const float* bq = (const float*)d_in[3];
    const float* Wk = (const float*)d_in[4];
    const float* bk = (const float*)d_in[5];
    const float* Wv = (const float*)d_in[6];
    const float* bv = (const float*)d_in[7];
    const float* Wo = (const float*)d_in[8];
    const float* bo = (const float*)d_in[9];
    float* out = (float*)d_out;

    __nv_bfloat16 *xh, *xl;
    cudaGetSymbolAddress((void**)&xh, g_xh);
    cudaGetSymbolAddress((void**)&xl, g_xl);

    cudaFuncSetAttribute(qkv_hmma_kernel,
                         cudaFuncAttributeMaxDynamicSharedMemorySize, HMMA_SMEM);
    cudaFuncSetAttribute(oproj_hmma_kernel,
                         cudaFuncAttributeMaxDynamicSharedMemorySize, HMMA_SMEM);
    cudaFuncSetAttribute(flash_hmma_kernel,
                         cudaFuncAttributeMaxDynamicSharedMemorySize, FLASH_SMEM);

    // Splits: x + all four weights
    split_kernel<<<(MROWS*CC/4 + 255)/256, 256>>>(x, xh, xl, MROWS*CC/4);
    split_w_kernel<<<(2*WQ4 + 2*WK4 + 255)/256, 256>>>(Wq, Wk, Wv, Wo);

    // QKV projection + bias + RoPE, writing split-bf16 Q/K and transposed V
    qkv_hmma_kernel<<<dim3(10, MROWS/128), 256, HMMA_SMEM>>>(rc, bq, bk, bv);

    // Causal flash attention (HMMA, 3-term split-bf16), split-bf16 output
    flash_hmma_kernel<<<dim3(TT/64, HQ, BB), 128, FLASH_SMEM>>>();

    // Output projection (HMMA, split-bf16)
    oproj_hmma_kernel<<<dim3(CC/128, MROWS/128), 256, HMMA_SMEM>>>(bo, out);
}

// round 11
// speedup vs baseline: 1.1783x; 1.1783x over previous
#include <cuda_runtime.h>
#include <cuda_bf16.h>
#include <stdint.h>

typedef unsigned long long u64;
typedef unsigned int u32;

#define BB 2
#define TT 2048
#define CC 1024
#define HQ 16
#define HKV 2
#define HD 64
#define MROWS (BB*TT)   // 4096

// ---------------------------------------------------------------------------
// Scratch (device globals; allocation APIs are forbidden)
// ---------------------------------------------------------------------------
__device__ __nv_bfloat16 g_xh[MROWS*CC], g_xl[MROWS*CC];
__device__ __nv_bfloat16 g_yh[MROWS*CC], g_yl[MROWS*CC];
__device__ __nv_bfloat16 g_wqh[CC*CC],  g_wql[CC*CC];
__device__ __nv_bfloat16 g_wkh[HKV*HD*CC], g_wkl[HKV*HD*CC];
__device__ __nv_bfloat16 g_wvh[HKV*HD*CC], g_wvl[HKV*HD*CC];
__device__ __nv_bfloat16 g_woh[CC*CC],  g_wol[CC*CC];

// split-bf16 Q/K (row-major) and V (transposed [b][hk][d][t])
__device__ __nv_bfloat16 g_qbh[MROWS*HQ*HD],  g_qbl[MROWS*HQ*HD];
__device__ __nv_bfloat16 g_kbh[MROWS*HKV*HD], g_kbl[MROWS*HKV*HD];
__device__ __nv_bfloat16 g_vth[BB*HKV*HD*TT], g_vtl[BB*HKV*HD*TT];

// ---------------------------------------------------------------------------
__device__ __forceinline__ u32 smem_to_u32(const void* p) {
    u32 a;
    asm("{ .reg .u64 tmp; cvta.to.shared.u64 tmp, %1; cvt.u32.u64 %0, tmp; }"
        : "=r"(a) : "l"(p));
    return a;
}
__device__ __forceinline__ void ldm_x4(u32* r, u32 addr) {
    asm volatile("ldmatrix.sync.aligned.m8n8.x4.shared.b16 {%0,%1,%2,%3}, [%4];"
        : "=r"(r[0]), "=r"(r[1]), "=r"(r[2]), "=r"(r[3]) : "r"(addr));
}
__device__ __forceinline__ void hmma(float* d, const u32* a, const u32* b) {
    asm volatile("mma.sync.aligned.m16n8k16.row.col.f32.bf16.bf16.f32 "
        "{%0,%1,%2,%3}, {%4,%5,%6,%7}, {%8,%9}, {%0,%1,%2,%3};"
        : "+f"(d[0]), "+f"(d[1]), "+f"(d[2]), "+f"(d[3])
        : "r"(a[0]), "r"(a[1]), "r"(a[2]), "r"(a[3]), "r"(b[0]), "r"(b[1]));
}
__device__ __forceinline__ u32 cvt2(float hi, float lo) {
    u32 r; asm("cvt.rn.bf16x2.f32 %0, %1, %2;" : "=r"(r) : "f"(hi), "f"(lo));
    return r;
}

// ---------------------------------------------------------------------------
// Split fp32 -> (hi, lo) bf16
// ---------------------------------------------------------------------------
__device__ __forceinline__ void split_body(
    const float* __restrict__ src, __nv_bfloat16* __restrict__ h,
    __nv_bfloat16* __restrict__ l, int i)
{
    float4 v = ((const float4*)src)[i];
    float vv[4] = { v.x, v.y, v.z, v.w };
    __nv_bfloat162 hh[2], ll[2];
    #pragma unroll
    for (int j = 0; j < 2; ++j) {
        __nv_bfloat16 h0 = __float2bfloat16(vv[2*j]);
        __nv_bfloat16 h1 = __float2bfloat16(vv[2*j+1]);
        hh[j].x = h0; hh[j].y = h1;
        ll[j].x = __float2bfloat16(vv[2*j]   - __bfloat162float(h0));
        ll[j].y = __float2bfloat16(vv[2*j+1] - __bfloat162float(h1));
    }
    ((__nv_bfloat162*)h)[2*i]   = hh[0];
    ((__nv_bfloat162*)h)[2*i+1] = hh[1];
    ((__nv_bfloat162*)l)[2*i]   = ll[0];
    ((__nv_bfloat162*)l)[2*i+1] = ll[1];
}

__global__ void split_kernel(const float* __restrict__ src,
                             __nv_bfloat16* __restrict__ h,
                             __nv_bfloat16* __restrict__ l, int n4)
{
    int i = blockIdx.x * blockDim.x + threadIdx.x;
    if (i >= n4) return;
    split_body(src, h, l, i);
}

// All four weights in one launch (sizes in float4 units)
#define WQ4 (CC*CC/4)          // 262144
#define WK4 (HKV*HD*CC/4)      // 32768
__global__ void split_w_kernel(const float* __restrict__ Wq,
                               const float* __restrict__ Wk,
                               const float* __restrict__ Wv,
                               const float* __restrict__ Wo)
{
    int i = blockIdx.x * blockDim.x + threadIdx.x;
    if (i < WQ4) { split_body(Wq, g_wqh, g_wql, i); return; }
    i -= WQ4;
    if (i < WK4) { split_body(Wk, g_wkh, g_wkl, i); return; }
    i -= WK4;
    if (i < WK4) { split_body(Wv, g_wvh, g_wvl, i); return; }
    i -= WK4;
    if (i < WQ4) { split_body(Wo, g_woh, g_wol, i); return; }
}

// ---------------------------------------------------------------------------
// HMMA bf16 split-GEMM tile: acc[128,128] = A[128,K].B[128,K]^T (+bias)
// Double-buffered smem (round-6/7 version, measured fastest).
// mode 0: fp32 out (no rope)
// mode 1: rope + split-bf16 row-major out (Q, K)
// mode 2: split-bf16 transposed out for V ([b][hk][d][t])
// ---------------------------------------------------------------------------
#define SPB 144
#define MAT_BYTES (128*SPB)
#define STAGE_BYTES (4*MAT_BYTES)
#define HMMA_SMEM (2*STAGE_BYTES)       // 147456

__device__ __forceinline__ void hmma_tile_128(
    const __nv_bfloat16* __restrict__ Ah, const __nv_bfloat16* __restrict__ Al,
    const __nv_bfloat16* __restrict__ Bh, const __nv_bfloat16* __restrict__ Bl,
    const float* __restrict__ bias, const float* __restrict__ rc,
    int m0, int n0, int ldo, int mode, float postscale,
    float* __restrict__ outf,
    __nv_bfloat16* __restrict__ outh, __nv_bfloat16* __restrict__ outl)
{
    extern __shared__ char smem[];
    const u32 sbase = smem_to_u32(smem);
    const int tid = threadIdx.x;
    const int wid = tid >> 5, L = tid & 31;
    const int wm = (wid >> 2) * 64;
    const int wn = (wid & 3) * 32;

    const u32 aRow = (u32)(wm + (L & 15)) * SPB + ((L >> 4) & 1) * 16;
    const u32 bRow = (u32)(wn + (((L >> 4) & 1) << 3) + (L & 7)) * SPB
                   + ((L >> 3) & 1) * 16;

    float acc[4][4][4];
    #pragma unroll
    for (int i = 0; i < 4; ++i)
        #pragma unroll
        for (int j = 0; j < 4; ++j)
            #pragma unroll
            for (int c = 0; c < 4; ++c) acc[i][j][c] = 0.f;

    float4 pA[4], pAl[4], pB[4], pBl[4];

    #pragma unroll
    for (int i = 0; i < 4; ++i) {
        const int it = tid + 256*i;
        const int row = it >> 3, ch = it & 7;
        const size_t ga = (size_t)(m0 + row) * CC + ch*8;
        const size_t gb = (size_t)(n0 + row) * CC + ch*8;
        const u32 so = (u32)row * SPB + ch*16;
        *(float4*)(smem + so)               = *(const float4*)(Ah + ga);
        *(float4*)(smem + MAT_BYTES + so)   = *(const float4*)(Al + ga);
        *(float4*)(smem + 2*MAT_BYTES + so) = *(const float4*)(Bh + gb);
        *(float4*)(smem + 3*MAT_BYTES + so) = *(const float4*)(Bl + gb);
    }
    __syncthreads();

    const int nslab = CC / 64;
    for (int s = 0; s < nslab; ++s) {
        const int p = s & 1;
        const bool more = (s + 1 < nslab);
        if (more) {
            const int k0 = (s + 1) * 64;
            #pragma unroll
            for (int i = 0; i < 4; ++i) {
                const int it = tid + 256*i;
                const int row = it >> 3, ch = it & 7;
                const size_t ga = (size_t)(m0 + row) * CC + k0 + ch*8;
                const size_t gb = (size_t)(n0 + row) * CC + k0 + ch*8;
                pA[i]  = *(const float4*)(Ah + ga);
                pAl[i] = *(const float4*)(Al + ga);
                pB[i]  = *(const float4*)(Bh + gb);
                pBl[i] = *(const float4*)(Bl + gb);
            }
        }

        const u32 st = sbase + p * STAGE_BYTES;
        const u32 aAh = st + aRow;
        const u32 aAl = st + MAT_BYTES + aRow;
        const u32 aBh = st + 2*MAT_BYTES + bRow;
        const u32 aBl = st + 3*MAT_BYTES + bRow;

        #pragma unroll
        for (int ks = 0; ks < 4; ++ks) {
            u32 ah[4][4], al[4][4], bh[4][2], bl[4][2];
            #pragma unroll
            for (int mt = 0; mt < 4; ++mt) {
                ldm_x4(ah[mt], aAh + mt*(16*SPB) + ks*32);
                ldm_x4(al[mt], aAl + mt*(16*SPB) + ks*32);
            }
            #pragma unroll
            for (int np = 0; np < 2; ++np) {
                u32 r[4];
                ldm_x4(r, aBh + np*(16*SPB) + ks*32);
                bh[2*np][0] = r[0]; bh[2*np][1] = r[1];
                bh[2*np+1][0] = r[2]; bh[2*np+1][1] = r[3];
                ldm_x4(r, aBl + np*(16*SPB) + ks*32);
                bl[2*np][0] = r[0]; bl[2*np][1] = r[1];
                bl[2*np+1][0] = r[2]; bl[2*np+1][1] = r[3];
            }
            #pragma unroll
            for (int mt = 0; mt < 4; ++mt)
                #pragma unroll
                for (int nt = 0; nt < 4; ++nt) {
                    hmma(acc[mt][nt], ah[mt], bh[nt]);
                    hmma(acc[mt][nt], ah[mt], bl[nt]);
                    hmma(acc[mt][nt], al[mt], bh[nt]);
                }
        }

        if (more) {
            char* dst = smem + (p ^ 1) * STAGE_BYTES;
            #pragma unroll
            for (int i = 0; i < 4; ++i) {
                const int it = tid + 256*i;
                const int row = it >> 3, ch = it & 7;
                const u32 so = (u32)row * SPB + ch*16;
                *(float4*)(dst + so)               = pA[i];
                *(float4*)(dst + MAT_BYTES + so)   = pAl[i];
                *(float4*)(dst + 2*MAT_BYTES + so) = pB[i];
                *(float4*)(dst + 3*MAT_BYTES + so) = pBl[i];
            }
            __syncthreads();
        }
    }

    // Epilogue
    #pragma unroll
    for (int mt = 0; mt < 4; ++mt) {
        #pragma unroll
        for (int nt = 0; nt < 4; ++nt) {
            const int n = n0 + wn + nt*8 + (L & 3) * 2;
            const float2 bv = *(const float2*)(bias + n);
            #pragma unroll
            for (int half = 0; half < 2; ++half) {
                const int r = m0 + wm + mt*16 + (L >> 2) + half*8;
                float v0 = acc[mt][nt][2*half]   + bv.x;
                float v1 = acc[mt][nt][2*half+1] + bv.y;
                if (mode == 1) {
                    const int t = r & (TT - 1);
                    const int d = n & (HD - 1);
                    const float2 rcv = *(const float2*)(rc + t*HD + d);
                    const float o0 = (v0 * rcv.y - v1 * rcv.x) * postscale;
                    const float o1 = (v1 * rcv.y + v0 * rcv.x) * postscale;
                    v0 = o0; v1 = o1;
                }
                if (mode == 0) {
                    float2 sv; sv.x = v0; sv.y = v1;
                    *(float2*)(outf + (size_t)r * ldo + n) = sv;
                } else {
                    const __nv_bfloat16 h0 = __float2bfloat16(v0);
                    const __nv_bfloat16 h1 = __float2bfloat16(v1);
                    const __nv_bfloat16 l0 = __float2bfloat16(v0 - __bfloat162float(h0));
                    const __nv_bfloat16 l1 = __float2bfloat16(v1 - __bfloat162float(h1));
                    if (mode == 1) {
                        __nv_bfloat162 hh; hh.x = h0; hh.y = h1;
                        __nv_bfloat162 ll; ll.x = l0; ll.y = l1;
                        *(__nv_bfloat162*)(outh + (size_t)r * ldo + n) = hh;
                        *(__nv_bfloat162*)(outl + (size_t)r * ldo + n) = ll;
                    } else {  // mode 2: V transposed [b][hk][d][t]
                        const int bb = r >> 11, t = r & (TT - 1);
                        const int hkv = n >> 6, d = n & (HD - 1);
                        const size_t base = (((size_t)bb*HKV + hkv)*HD + d)*TT + t;
                        outh[base] = h0; outh[base + TT] = h1;
                        outl[base] = l0; outl[base + TT] = l1;
                    }
                }
            }
        }
    }
}

// grid (10, 32): x 0..7 -> Q col tiles, 8 -> K, 9 -> V
__global__ __launch_bounds__(256) void qkv_hmma_kernel(
    const float* __restrict__ rc,
    const float* __restrict__ bq, const float* __restrict__ bk,
    const float* __restrict__ bv)
{
    const int nb = blockIdx.x, m0 = blockIdx.y * 128;
    if (nb < 8)
        hmma_tile_128(g_xh, g_xl, g_wqh, g_wql, bq, rc, m0, nb*128, HQ*HD,
                      1, 1.0f/(float)HD, nullptr, g_qbh, g_qbl);
    else if (nb == 8)
        hmma_tile_128(g_xh, g_xl, g_wkh, g_wkl, bk, rc, m0, 0, HKV*HD,
                      1, 1.0f, nullptr, g_kbh, g_kbl);
    else
        hmma_tile_128(g_xh, g_xl, g_wvh, g_wvl, bv, nullptr, m0, 0, HKV*HD,
                      2, 1.0f, nullptr, g_vth, g_vtl);
}

__global__ __launch_bounds__(256) void oproj_hmma_kernel(
    const float* __restrict__ bo, float* __restrict__ out)
{
    hmma_tile_128(g_yh, g_yl, g_woh, g_wol, bo, nullptr,
                  blockIdx.y*128, blockIdx.x*128, CC, 0, 1.0f,
                  out, nullptr, nullptr);
}

// ---------------------------------------------------------------------------
// Flash attention on HMMA. grid (T/64, HQ, B), 128 threads (4 warps).
// Longest-first scheduling: blockIdx.x=0 -> qb=31 (LPT).
// Writes O as split-bf16 directly into g_yh/g_yl.
// ---------------------------------------------------------------------------
#define FP 72                       // smem pitch in bf16 (144 B)
#define MATB (64*FP*2)              // 9216 B per matrix
#define FLASH_SMEM (6*MATB)         // 55296 B

__global__ __launch_bounds__(128) void flash_hmma_kernel()
{
    extern __shared__ __nv_bfloat16 fsm[];
    const u32 sb = smem_to_u32(fsm);
    // matrices: Qh@0, Ql@MATB, Kh@2*MATB, Kl@3*MATB, Vth@4*MATB, Vtl@5*MATB

    const int qb = (int)gridDim.x - 1 - (int)blockIdx.x;   // longest first
    const int hq = blockIdx.y, b = blockIdx.z;
    const int qs = qb * 64;
    const int hk = hq / (HQ / HKV);
    const int tid = threadIdx.x, wid = tid >> 5, L = tid & 31;

    // stage Q (64 rows x 64 bf16, hi+lo)
    for (int it = tid; it < 512; it += 128) {
        const int row = it >> 3, ch = it & 7;
        const size_t src = (((size_t)b*TT + qs + row)*HQ + hq)*HD + ch*8;
        *(float4*)&fsm[row*FP + ch*8]            = *(const float4*)(g_qbh + src);
        *(float4*)&fsm[64*FP + row*FP + ch*8]    = *(const float4*)(g_qbl + src);
    }

    // fragment address offsets (bytes)
    const u32 aQoff = (u32)((wid*16 + (L & 15)) * SPB) + ((L >> 4) & 1) * 16;
    const u32 aVrow = (u32)((L & 15) * SPB) + ((L >> 4) & 1) * 16;
    const u32 bKoff = (u32)((((L >> 4) & 1) * 8 + (L & 7)) * SPB) + ((L >> 3) & 1) * 16;

    float m0 = -1e30f, m1 = -1e30f, ls0 = 0.f, ls1 = 0.f;
    float oacc[4][2][4];
    #pragma unroll
    for (int i = 0; i < 4; ++i)
        #pragma unroll
        for (int j = 0; j < 2; ++j)
            #pragma unroll
            for (int c = 0; c < 4; ++c) oacc[i][j][c] = 0.f;

    for (int kt = 0; kt <= qb; ++kt) {
        __syncthreads();
        // stage K (rows t), V^T (rows d)
        for (int it = tid; it < 512; it += 128) {
            const int row = it >> 3, ch = it & 7;
            const size_t ks = (((size_t)b*TT + kt*64 + row)*HKV + hk)*HD + ch*8;
            const size_t vs = (((size_t)b*HKV + hk)*HD + row)*TT + kt*64 + ch*8;
            *(float4*)&fsm[2*64*FP + row*FP + ch*8] = *(const float4*)(g_kbh + ks);
            *(float4*)&fsm[3*64*FP + row*FP + ch*8] = *(const float4*)(g_kbl + ks);
            *(float4*)&fsm[4*64*FP + row*FP + ch*8] = *(const float4*)(g_vth + vs);
            *(float4*)&fsm[5*64*FP + row*FP + ch*8] = *(const float4*)(g_vtl + vs);
        }
        __syncthreads();

        // ---- S = Q.K^T (3-term) ----
        float sacc[8][4];
        #pragma unroll
        for (int nt = 0; nt < 8; ++nt)
            #pragma unroll
            for (int c = 0; c < 4; ++c) sacc[nt][c] = 0.f;

        #pragma unroll
        for (int ks = 0; ks < 4; ++ks) {
            u32 qh_[4], ql_[4];
            ldm_x4(qh_, sb + aQoff + ks*32);
            ldm_x4(ql_, sb + MATB + aQoff + ks*32);
            #pragma unroll
            for (int np = 0; np < 4; ++np) {
                u32 rh[4], rl[4];
                const u32 bo = (u32)(np*16*SPB) + bKoff + ks*32;
                ldm_x4(rh, sb + 2*MATB + bo);
                ldm_x4(rl, sb + 3*MATB + bo);
                u32 bh0[2] = { rh[0], rh[1] }, bh1[2] = { rh[2], rh[3] };
                u32 bl0[2] = { rl[0], rl[1] }, bl1[2] = { rl[2], rl[3] };
                hmma(sacc[2*np],   qh_, bh0);
                hmma(sacc[2*np],   qh_, bl0);
                hmma(sacc[2*np],   ql_, bh0);
                hmma(sacc[2*np+1], qh_, bh1);
                hmma(sacc[2*np+1], qh_, bl1);
                hmma(sacc[2*np+1], ql_, bh1);
            }
        }

        // ---- causal mask (diagonal tile only) ----
        if (kt == qb) {
            #pragma unroll
            for (int nt = 0; nt < 8; ++nt)
                #pragma unroll
                for (int c = 0; c < 4; ++c) {
                    const int col = nt*8 + (L & 3)*2 + (c & 1);
                    const int row = wid*16 + (L >> 2) + ((c >> 1) & 1)*8;
                    if (col > row) sacc[nt][c] = -1e30f;
                }
        }

        // ---- online softmax ----
        float mx0 = -1e30f, mx1 = -1e30f;
        #pragma unroll
        for (int nt = 0; nt < 8; ++nt) {
            mx0 = fmaxf(mx0, fmaxf(sacc[nt][0], sacc[nt][1]));
            mx1 = fmaxf(mx1, fmaxf(sacc[nt][2], sacc[nt][3]));
        }
        mx0 = fmaxf(mx0, __shfl_xor_sync(0xffffffffu, mx0, 1));
        mx0 = fmaxf(mx0, __shfl_xor_sync(0xffffffffu, mx0, 2));
        mx1 = fmaxf(mx1, __shfl_xor_sync(0xffffffffu, mx1, 1));
        mx1 = fmaxf(mx1, __shfl_xor_sync(0xffffffffu, mx1, 2));
        const float nm0 = fmaxf(m0, mx0);
        const float nm1 = fmaxf(m1, mx1);
        const float corr0 = __expf(m0 - nm0);
        const float corr1 = __expf(m1 - nm1);
        m0 = nm0; m1 = nm1;

        u32 ph0[8], ph1[8], pl0[8], pl1[8];
        float rs0 = 0.f, rs1 = 0.f;
        #pragma unroll
        for (int nt = 0; nt < 8; ++nt) {
            const float p00 = __expf(sacc[nt][0] - nm0);
            const float p01 = __expf(sacc[nt][1] - nm0);
            const float p10 = __expf(sacc[nt][2] - nm1);
            const float p11 = __expf(sacc[nt][3] - nm1);
            rs0 += p00 + p01;
            rs1 += p10 + p11;
            ph0[nt] = cvt2(p01, p00);
            ph1[nt] = cvt2(p11, p10);
            pl0[nt] = cvt2(p01 - __bfloat162float(__float2bfloat16(p01)),
                           p00 - __bfloat162float(__float2bfloat16(p00)));
            pl1[nt] = cvt2(p11 - __bfloat162float(__float2bfloat16(p11)),
                           p10 - __bfloat162float(__float2bfloat16(p10)));
        }
        rs0 += __shfl_xor_sync(0xffffffffu, rs0, 1);
        rs0 += __shfl_xor_sync(0xffffffffu, rs0, 2);
        rs1 += __shfl_xor_sync(0xffffffffu, rs1, 1);
        rs1 += __shfl_xor_sync(0xffffffffu, rs1, 2);
        ls0 = ls0 * corr0 + rs0;
        ls1 = ls1 * corr1 + rs1;

        // rescale O^T accumulators
        float cr[2][2];
        cr[0][0] = __shfl_sync(0xffffffffu, corr0, ((L & 3)*2)     << 2);
        cr[0][1] = __shfl_sync(0xffffffffu, corr0, ((L & 3)*2 + 1) << 2);
        cr[1][0] = __shfl_sync(0xffffffffu, corr1, ((L & 3)*2)     << 2);
        cr[1][1] = __shfl_sync(0xffffffffu, corr1, ((L & 3)*2 + 1) << 2);
        #pragma unroll
        for (int mt = 0; mt < 4; ++mt)
            #pragma unroll
            for (int nu = 0; nu < 2; ++nu)
                #pragma unroll
                for (int c = 0; c < 4; ++c)
                    oacc[mt][nu][c] *= cr[nu][c & 1];

        // ---- O^T += V^T.P^T (3-term) ----
        #pragma unroll
        for (int k2 = 0; k2 < 4; ++k2) {
            u32 bH0[2] = { ph0[2*k2], ph0[2*k2+1] };
            u32 bH1[2] = { ph1[2*k2], ph1[2*k2+1] };
            u32 bL0[2] = { pl0[2*k2], pl0[2*k2+1] };
            u32 bL1[2] = { pl1[2*k2], pl1[2*k2+1] };
            #pragma unroll
            for (int mt = 0; mt < 4; ++mt) {
                u32 vh_[4], vl_[4];
                const u32 vo = aVrow + (u32)(mt*16*SPB) + k2*32;
                ldm_x4(vh_, sb + 4*MATB + vo);
                ldm_x4(vl_, sb + 5*MATB + vo);
                hmma(oacc[mt][0], vh_, bH0);
                hmma(oacc[mt][0], vl_, bH0);
                hmma(oacc[mt][0], vh_, bL0);
                hmma(oacc[mt][1], vh_, bH1);
                hmma(oacc[mt][1], vl_, bH1);
                hmma(oacc[mt][1], vh_, bL1);
            }
        }
    }

    // ---- normalize + write split-bf16 O into g_yh/g_yl ([b][t][h][d]) ----
    const float rl0 = 1.f / ls0, rl1 = 1.f / ls1;
    float iv[2][2];
    iv[0][0] = __shfl_sync(0xffffffffu, rl0, ((L & 3)*2)     << 2);
    iv[0][1] = __shfl_sync(0xffffffffu, rl0, ((L & 3)*2 + 1) << 2);
    iv[1][0] = __shfl_sync(0xffffffffu, rl1, ((L & 3)*2)     << 2);
    iv[1][1] = __shfl_sync(0xffffffffu, rl1, ((L & 3)*2 + 1) << 2);
    #pragma unroll
    for (int mt = 0; mt < 4; ++mt)
        #pragma unroll
        for (int nu = 0; nu < 2; ++nu)
            #pragma unroll
            for (int c = 0; c < 4; ++c) {
                const int d = mt*16 + (L >> 2) + ((c >> 1) & 1)*8;
                const int i = nu*8 + (L & 3)*2 + (c & 1);
                const float o = oacc[mt][nu][c] * iv[nu][c & 1];
                const __nv_bfloat16 oh = __float2bfloat16(o);
                const __nv_bfloat16 ol = __float2bfloat16(o - __bfloat162float(oh));
                const size_t idx =
                    (((size_t)b*TT + qs + wid*16 + i)*HQ + hq)*HD + d;
                g_yh[idx] = oh;
                g_yl[idx] = ol;
            }
}

// ---------------------------------------------------------------------------
extern "C" void kernel_launch(void* const* d_in, const int* in_sizes, int n_in,
                              void* d_out, int out_size)
{
    const float* x  = (const float*)d_in[0];
    const float* rc = (const float*)d_in[1];
    const float* Wq = (const float*)d_in[2];
    const float* bq = (const float*)d_in[3];
    const float* Wk = (const float*)d_in[4];
    const float* bk = (const float*)d_in[5];
    const float* Wv = (const float*)d_in[6];
    const float* bv = (const float*)d_in[7];
    const float* Wo = (const float*)d_in[8];
    const float* bo = (const float*)d_in[9];
    float* out = (float*)d_out;

    __nv_bfloat16 *xh, *xl;
    cudaGetSymbolAddress((void**)&xh, g_xh);
    cudaGetSymbolAddress((void**)&xl, g_xl);

    cudaFuncSetAttribute(qkv_hmma_kernel,
                         cudaFuncAttributeMaxDynamicSharedMemorySize, HMMA_SMEM);
    cudaFuncSetAttribute(oproj_hmma_kernel,
                         cudaFuncAttributeMaxDynamicSharedMemorySize, HMMA_SMEM);
    cudaFuncSetAttribute(flash_hmma_kernel,
                         cudaFuncAttributeMaxDynamicSharedMemorySize, FLASH_SMEM);

    // Splits: x + all four weights
    split_kernel<<<(MROWS*CC/4 + 255)/256, 256>>>(x, xh, xl, MROWS*CC/4);
    split_w_kernel<<<(2*WQ4 + 2*WK4 + 255)/256, 256>>>(Wq, Wk, Wv, Wo);

    // QKV projection + bias + RoPE, writing split-bf16 Q/K and transposed V
    qkv_hmma_kernel<<<dim3(10, MROWS/128), 256, HMMA_SMEM>>>(rc, bq, bk, bv);

    // Causal flash attention (HMMA, 3-term split-bf16), split-bf16 output
    flash_hmma_kernel<<<dim3(TT/64, HQ, BB), 128, FLASH_SMEM>>>();

    // Output projection (HMMA, split-bf16)
    oproj_hmma_kernel<<<dim3(CC/128, MROWS/128), 256, HMMA_SMEM>>>(bo, out);
}